// round 9
// baseline (speedup 1.0000x reference)
#include <cuda_runtime.h>
#include <cuda_bf16.h>
#include <math.h>
#include <stdint.h>

// Problem constants
#define D_MODEL 256
#define B_      4
#define TQ_     9
#define TS_     8
#define HW_     1024
#define NH_     8
#define DH_     32
#define MLP_    1024

constexpr int MS = B_ * TS_ * HW_;   // 32768 spatial tokens
constexpr int MT = B_ * TQ_ * HW_;   // 36864 full tokens

// Scratch (device globals — no allocations allowed)
__device__ __align__(128) __nv_bfloat16 g_lnb [MT * D_MODEL];
__device__ __align__(128) __nv_bfloat16 g_qkvb[MT * 768];
__device__ __align__(128) __nv_bfloat16 g_aob [MT * D_MODEL];
__device__ __align__(128) float         g_x   [MT * D_MODEL];
__device__ __align__(128) float         g_y   [MT * D_MODEL];
__device__ __align__(128) float         g_tmp [MT * D_MODEL];
__device__ __align__(128) __nv_bfloat16 g_hidb[MT * MLP_];
// packed bf16 weights
__device__ __align__(128) __nv_bfloat16 g_wsp[D_MODEL * 768];
__device__ __align__(128) __nv_bfloat16 g_wtp[D_MODEL * 768];
__device__ __align__(128) __nv_bfloat16 g_wso[D_MODEL * D_MODEL];
__device__ __align__(128) __nv_bfloat16 g_wto[D_MODEL * D_MODEL];
__device__ __align__(128) __nv_bfloat16 g_w1 [D_MODEL * MLP_];
__device__ __align__(128) __nv_bfloat16 g_w2 [MLP_ * D_MODEL];
__device__ float g_bsp[768];
__device__ float g_btp[768];
__device__ float g_clsp[B_ * 8 * D_MODEL];

// ---------------------------------------------------------------------------
// Fused convert/pack: weights fp32 -> bf16 (keeping [K][N] layout), + biases
// ---------------------------------------------------------------------------
__global__ __launch_bounds__(256)
void pack_all_kernel(const float* __restrict__ s_wq, const float* __restrict__ s_wk,
                     const float* __restrict__ s_wv, const float* __restrict__ t_wq,
                     const float* __restrict__ t_wk, const float* __restrict__ t_wv,
                     const float* __restrict__ s_wo, const float* __restrict__ t_wo,
                     const float* __restrict__ w1,   const float* __restrict__ w2,
                     const float* __restrict__ s_bq, const float* __restrict__ s_bk,
                     const float* __restrict__ s_bv, const float* __restrict__ t_bq,
                     const float* __restrict__ t_bk, const float* __restrict__ t_bv,
                     __nv_bfloat16* __restrict__ wsp, __nv_bfloat16* __restrict__ wtp,
                     __nv_bfloat16* __restrict__ wso, __nv_bfloat16* __restrict__ wto,
                     __nv_bfloat16* __restrict__ wb1, __nv_bfloat16* __restrict__ wb2,
                     float* __restrict__ bsp, float* __restrict__ btp)
{
    int blk = blockIdx.x;
    int tid = threadIdx.x;
    if (blk >= 1024) {                      // bias pack block
        if (tid < 256) {
            bsp[tid] = s_bq[tid]; bsp[256 + tid] = s_bk[tid]; bsp[512 + tid] = s_bv[tid];
            btp[tid] = t_bq[tid]; btp[256 + tid] = t_bk[tid]; btp[512 + tid] = t_bv[tid];
        }
        return;
    }
    const float* src; __nv_bfloat16* dst;
    int t, Nsrc, Ndst, nOff;
    if (blk < 384) {                        // 6 x 64 blocks for qkv packs
        int m = blk / 64; t = blk % 64; Nsrc = 256; Ndst = 768;
        const float* s6[6] = {s_wq, s_wk, s_wv, t_wq, t_wk, t_wv};
        src = s6[m]; dst = (m < 3) ? wsp : wtp; nOff = (m % 3) * 256;
    } else if (blk < 448) { t = blk - 384; src = s_wo; dst = wso; Nsrc = 256;  Ndst = 256;  nOff = 0; }
    else   if (blk < 512) { t = blk - 448; src = t_wo; dst = wto; Nsrc = 256;  Ndst = 256;  nOff = 0; }
    else   if (blk < 768) { t = blk - 512; src = w1;   dst = wb1; Nsrc = 1024; Ndst = 1024; nOff = 0; }
    else                  { t = blk - 768; src = w2;   dst = wb2; Nsrc = 256;  Ndst = 256;  nOff = 0; }

    int i = t * 1024 + tid * 4;             // 1024 elems per block, 4 per thread
    const float4 v = *(const float4*)&src[i];
    int k = i / Nsrc, n = i - k * Nsrc;
    __nv_bfloat16* d = &dst[(size_t)k * Ndst + nOff + n];
    d[0] = __float2bfloat16(v.x); d[1] = __float2bfloat16(v.y);
    d[2] = __float2bfloat16(v.z); d[3] = __float2bfloat16(v.w);
}

// ---------------------------------------------------------------------------
// LayerNorm: one warp per token, bf16 output
// ---------------------------------------------------------------------------
__global__ void ln_kernel(const float* __restrict__ src, __nv_bfloat16* __restrict__ dst,
                          const float* __restrict__ gam, const float* __restrict__ bet,
                          int M, int src_tpb, int dst_tpb)
{
    int warp = (blockIdx.x * blockDim.x + threadIdx.x) >> 5;
    int lane = threadIdx.x & 31;
    if (warp >= M) return;
    int bb = warp / dst_tpb;
    int rem = warp % dst_tpb;
    const float* x = src + ((size_t)bb * src_tpb + rem) * D_MODEL;

    float vals[8];
    float s = 0.f, s2 = 0.f;
#pragma unroll
    for (int j = 0; j < 8; j++) {
        float v = x[lane + 32 * j];
        vals[j] = v; s += v; s2 += v * v;
    }
#pragma unroll
    for (int o = 16; o; o >>= 1) {
        s  += __shfl_xor_sync(0xffffffffu, s,  o);
        s2 += __shfl_xor_sync(0xffffffffu, s2, o);
    }
    float mean = s * (1.f / D_MODEL);
    float var  = s2 * (1.f / D_MODEL) - mean * mean;
    float rstd = rsqrtf(var + 1e-5f);

    __nv_bfloat16* y = dst + (size_t)warp * D_MODEL;
#pragma unroll
    for (int j = 0; j < 8; j++) {
        int d = lane + 32 * j;
        y[d] = __float2bfloat16((vals[j] - mean) * rstd * gam[d] + bet[d]);
    }
}

// ---------------------------------------------------------------------------
// bf16 mma.sync GEMM: C[M,N] = A[M,K] @ W[K,N] + bias (+ GELU / residual)
// Block 128x128, BK=64, 3-stage cp.async pipeline, one barrier per K-step.
// 8 warps (2x4), warp tile 64x32, mma.m16n8k16, ldmatrix fragments.
// ---------------------------------------------------------------------------
#define BM 128
#define BN 128
#define BKB 64
#define A_PAD 72        // A row stride (bf16 elems)
#define B_PAD 136       // B row stride
#define A_STAGE_BYTES (BM * A_PAD * 2)          // 18432
#define B_STAGE_BYTES (BKB * B_PAD * 2)         // 17408
#define STAGE_BYTES   (A_STAGE_BYTES + B_STAGE_BYTES)
#define NSTAGE 3
#define SMEM_GEMM (STAGE_BYTES * NSTAGE)        // 107520

#define CP_ASYNC16(dst_u32, src_ptr) \
    asm volatile("cp.async.cg.shared.global [%0], [%1], 16;\n" :: "r"(dst_u32), "l"(src_ptr))
#define CP_COMMIT() asm volatile("cp.async.commit_group;\n" ::: "memory")

__device__ __forceinline__ void ldmx4(uint32_t& r0, uint32_t& r1, uint32_t& r2, uint32_t& r3,
                                      const void* p)
{
    uint32_t a = (uint32_t)__cvta_generic_to_shared(p);
    asm volatile("ldmatrix.sync.aligned.m8n8.x4.shared.b16 {%0,%1,%2,%3}, [%4];"
                 : "=r"(r0), "=r"(r1), "=r"(r2), "=r"(r3) : "r"(a));
}
__device__ __forceinline__ void ldmx4t(uint32_t& r0, uint32_t& r1, uint32_t& r2, uint32_t& r3,
                                       const void* p)
{
    uint32_t a = (uint32_t)__cvta_generic_to_shared(p);
    asm volatile("ldmatrix.sync.aligned.m8n8.x4.trans.shared.b16 {%0,%1,%2,%3}, [%4];"
                 : "=r"(r0), "=r"(r1), "=r"(r2), "=r"(r3) : "r"(a));
}
__device__ __forceinline__ void mma_bf16(float* d, const uint32_t* a, const uint32_t* b)
{
    asm volatile(
        "mma.sync.aligned.m16n8k16.row.col.f32.bf16.bf16.f32 "
        "{%0,%1,%2,%3}, {%4,%5,%6,%7}, {%8,%9}, {%0,%1,%2,%3};"
        : "+f"(d[0]), "+f"(d[1]), "+f"(d[2]), "+f"(d[3])
        : "r"(a[0]), "r"(a[1]), "r"(a[2]), "r"(a[3]), "r"(b[0]), "r"(b[1]));
}

__device__ __forceinline__ void storeC(float* p, float v)          { *p = v; }
__device__ __forceinline__ void storeC(__nv_bfloat16* p, float v)  { *p = __float2bfloat16(v); }

template <typename OutT, bool GELU, bool RES>
__global__ __launch_bounds__(256)
void gemm_bf16_kernel(const __nv_bfloat16* __restrict__ A, const __nv_bfloat16* __restrict__ W,
                      const float* __restrict__ bias, const float* __restrict__ res,
                      OutT* __restrict__ C, int M, int N, int K)
{
    extern __shared__ char smem[];

    const int tid  = threadIdx.x;
    const int lane = tid & 31;
    const int warp = tid >> 5;
    const int wm   = warp & 1;
    const int wn   = warp >> 1;
    const int m0 = blockIdx.y * BM;
    const int n0 = blockIdx.x * BN;
    const int wmo = wm * 64;
    const int wno = wn * 32;

    // staging: A tile 128 rows x 64 cols bf16 = 128 x 8 chunks(16B) = 1024 chunks
    //          each thread: row tid>>1, 4 chunks at cols (tid&1)*32 + {0,8,16,24}
    //          B tile 64 rows x 128 cols = 64 x 16 chunks = 1024 chunks
    //          each thread: row tid>>2, 4 chunks at cols (tid&3)*8 + {0,32,64,96}
    const int aR = tid >> 1, aCb = (tid & 1) * 32;
    const int bR = tid >> 2, bCb = (tid & 3) * 8;

    float acc[4][4][4];
#pragma unroll
    for (int i = 0; i < 4; i++)
#pragma unroll
        for (int j = 0; j < 4; j++)
#pragma unroll
            for (int r = 0; r < 4; r++) acc[i][j][r] = 0.f;

    auto a_stage = [&](int s) -> __nv_bfloat16* {
        return (__nv_bfloat16*)(smem + (s % NSTAGE) * STAGE_BYTES);
    };
    auto b_stage = [&](int s) -> __nv_bfloat16* {
        return (__nv_bfloat16*)(smem + (s % NSTAGE) * STAGE_BYTES + A_STAGE_BYTES);
    };

    auto load_stage = [&](int s) {
        int k0 = s * BKB;
        __nv_bfloat16* As = a_stage(s);
        __nv_bfloat16* Bs = b_stage(s);
#pragma unroll
        for (int h = 0; h < 4; h++) {
            int c = aCb + h * 8;
            CP_ASYNC16((uint32_t)__cvta_generic_to_shared(&As[aR * A_PAD + c]),
                       A + (size_t)(m0 + aR) * K + k0 + c);
        }
#pragma unroll
        for (int h = 0; h < 4; h++) {
            int c = bCb + h * 32;
            CP_ASYNC16((uint32_t)__cvta_generic_to_shared(&Bs[bR * B_PAD + c]),
                       W + (size_t)(k0 + bR) * N + n0 + c);
        }
        CP_COMMIT();
    };

    auto compute_stage = [&](int s) {
        __nv_bfloat16* As = a_stage(s);
        __nv_bfloat16* Bs = b_stage(s);
#pragma unroll
        for (int ks = 0; ks < BKB; ks += 16) {
            uint32_t af[4][4];
            uint32_t bf[4][2];
#pragma unroll
            for (int mt = 0; mt < 4; mt++) {
                ldmx4(af[mt][0], af[mt][1], af[mt][2], af[mt][3],
                      &As[(wmo + mt * 16 + (lane & 15)) * A_PAD + ks + (lane >> 4) * 8]);
            }
#pragma unroll
            for (int ng = 0; ng < 2; ng++) {
                uint32_t t0, t1, t2, t3;
                ldmx4t(t0, t1, t2, t3,
                       &Bs[(ks + (lane & 15)) * B_PAD + wno + ng * 16 + (lane >> 4) * 8]);
                bf[ng * 2][0] = t0; bf[ng * 2][1] = t1;
                bf[ng * 2 + 1][0] = t2; bf[ng * 2 + 1][1] = t3;
            }
#pragma unroll
            for (int mt = 0; mt < 4; mt++)
#pragma unroll
                for (int nt = 0; nt < 4; nt++)
                    mma_bf16(acc[mt][nt], af[mt], bf[nt]);
        }
    };

    const int nst = K / BKB;
    load_stage(0);
    if (nst > 1) load_stage(1);

    for (int s = 0; s < nst; s++) {
        if (s + 1 < nst) asm volatile("cp.async.wait_group 1;" ::: "memory");
        else             asm volatile("cp.async.wait_group 0;" ::: "memory");
        __syncthreads();
        if (s + 2 < nst) load_stage(s + 2);
        compute_stage(s);
        __syncthreads();
    }

    // epilogue: direct fragment stores
#pragma unroll
    for (int mt = 0; mt < 4; mt++) {
#pragma unroll
        for (int nt = 0; nt < 4; nt++) {
            int row0 = m0 + wmo + mt * 16 + (lane >> 2);
            int col0 = n0 + wno + nt * 8 + 2 * (lane & 3);
#pragma unroll
            for (int r = 0; r < 4; r++) {
                int row = row0 + (r >> 1) * 8;
                int col = col0 + (r & 1);
                float v = acc[mt][nt][r] + bias[col];
                if (GELU) v = 0.5f * v * (1.f + erff(v * 0.70710678118654752f));
                if (RES)  v += res[(size_t)row * N + col];
                storeC(&C[(size_t)row * N + col], v);
            }
        }
    }
}

// ---------------------------------------------------------------------------
// Spatial windowed attention: packed bf16 QKV (stride 768), bf16 output
// ---------------------------------------------------------------------------
__global__ __launch_bounds__(256)
void spatial_attn_kernel(const __nv_bfloat16* __restrict__ QKV, __nv_bfloat16* __restrict__ O)
{
    const int token = blockIdx.x;           // 0..32767
    const int head  = threadIdx.x >> 5;
    const int lane  = threadIdx.x & 31;
    const int hw = token & (HW_ - 1);
    const int r = hw >> 5, c = hw & 31;
    const size_t base = (size_t)token * 768 + head * DH_ + lane;
    const float scale = 0.17677669529663687f;   // 1/sqrt(32)

    const float q = __bfloat162float(QKV[base]);
    float sc[9];
    float mx = -1e30f;
#pragma unroll
    for (int n = 0; n < 9; n++) {
        int dr = n / 3 - 1, dc = n % 3 - 1;
        int rr = r + dr, cc = c + dc;
        bool ok = (rr >= 0) & (rr < 32) & (cc >= 0) & (cc < 32);
        float s = -1e9f;
        if (ok) {
            int t2 = token + dr * 32 + dc;
            float p = q * __bfloat162float(QKV[(size_t)t2 * 768 + 256 + head * DH_ + lane]);
#pragma unroll
            for (int o = 16; o; o >>= 1) p += __shfl_xor_sync(0xffffffffu, p, o);
            s = p * scale;
        }
        sc[n] = s;
        mx = fmaxf(mx, s);
    }
    float denom = 0.f;
#pragma unroll
    for (int n = 0; n < 9; n++) { sc[n] = expf(sc[n] - mx); denom += sc[n]; }
    float inv = 1.f / denom;

    float o_acc = 0.f;
#pragma unroll
    for (int n = 0; n < 9; n++) {
        int dr = n / 3 - 1, dc = n % 3 - 1;
        int rr = r + dr, cc = c + dc;
        bool ok = (rr >= 0) & (rr < 32) & (cc >= 0) & (cc < 32);
        if (ok) {
            int t2 = token + dr * 32 + dc;
            o_acc = fmaf(sc[n] * inv,
                         __bfloat162float(QKV[(size_t)t2 * 768 + 512 + head * DH_ + lane]),
                         o_acc);
        }
    }
    O[(size_t)token * D_MODEL + head * DH_ + lane] = __float2bfloat16(o_acc);
}

// ---------------------------------------------------------------------------
// Assemble x = concat(spatial_out + residual, last frame)
// ---------------------------------------------------------------------------
__global__ void assemble_x_kernel(const float* __restrict__ query,
                                  const float* __restrict__ sp,
                                  float* __restrict__ x)
{
    size_t i = (size_t)blockIdx.x * blockDim.x + threadIdx.x;
    const int per_bt = HW_ * D_MODEL;
    int bt = (int)(i / per_bt);
    int rem = (int)(i % per_bt);
    int b = bt / TQ_, t = bt % TQ_;
    float v = query[i];
    if (t < TS_) v += sp[(size_t)(b * TS_ + t) * per_bt + rem];
    x[i] = v;
}

// ---------------------------------------------------------------------------
// Temporal RoPE attention: packed bf16 QKV (stride 768), bf16 output
// ---------------------------------------------------------------------------
__global__ __launch_bounds__(256)
void temporal_attn_kernel(const __nv_bfloat16* __restrict__ QKV,
                          const unsigned char* __restrict__ mask,
                          __nv_bfloat16* __restrict__ O)
{
    const int seq  = blockIdx.x;        // b*1024 + hw
    const int head = threadIdx.x >> 5;
    const int lane = threadIdx.x & 31;
    const int b  = seq >> 10;
    const int hw = seq & (HW_ - 1);
    const size_t tstride = (size_t)HW_ * 768;
    const size_t base0 = ((size_t)(b * TQ_) * HW_ + hw) * 768 + head * DH_ + lane;
    const size_t ostride = (size_t)HW_ * D_MODEL;
    const size_t obase = ((size_t)(b * TQ_) * HW_ + hw) * D_MODEL + head * DH_ + lane;
    const float scale = 0.17677669529663687f;

    const int pi = lane & 15;
    const float inv = powf(10000.f, -(float)pi / 16.f);

    float qv[9], kv[9], vv[9];
#pragma unroll
    for (int t = 0; t < TQ_; t++) {
        float qq = __bfloat162float(QKV[base0 + t * tstride]);
        float kk = __bfloat162float(QKV[base0 + 256 + t * tstride]);
        vv[t]    = __bfloat162float(QKV[base0 + 512 + t * tstride]);
        float ang = (float)t * inv;
        float cs = cosf(ang), sn = sinf(ang);
        float qp = __shfl_xor_sync(0xffffffffu, qq, 16);
        float kp = __shfl_xor_sync(0xffffffffu, kk, 16);
        if (lane < 16) {
            qv[t] = qq * cs - qp * sn;
            kv[t] = kk * cs - kp * sn;
        } else {
            qv[t] = qp * sn + qq * cs;
            kv[t] = kp * sn + kk * cs;
        }
    }

#pragma unroll
    for (int tq = 0; tq < TQ_; tq++) {
        float sc[9];
        float mx = -1e30f;
#pragma unroll
        for (int tk = 0; tk < TQ_; tk++) {
            float p = qv[tq] * kv[tk];
#pragma unroll
            for (int o = 16; o; o >>= 1) p += __shfl_xor_sync(0xffffffffu, p, o);
            float s = p * scale;
            if (mask[tq * TQ_ + tk]) s = -1e9f;
            sc[tk] = s;
            mx = fmaxf(mx, s);
        }
        float denom = 0.f;
#pragma unroll
        for (int tk = 0; tk < TQ_; tk++) { sc[tk] = expf(sc[tk] - mx); denom += sc[tk]; }
        float invd = 1.f / denom;
        float o_acc = 0.f;
#pragma unroll
        for (int tk = 0; tk < TQ_; tk++) o_acc = fmaf(sc[tk] * invd, vv[tk], o_acc);
        O[obase + tq * ostride] = __float2bfloat16(o_acc);
    }
}

// ---------------------------------------------------------------------------
// CLS frame averaging, two-phase deterministic
// ---------------------------------------------------------------------------
__global__ void cls_p1_kernel(const float* __restrict__ y, float* __restrict__ part)
{
    int blk = blockIdx.x;           // 32 blocks = (b, chunk)
    int b = blk >> 3, ch = blk & 7;
    int d = threadIdx.x;            // 256
    size_t base = (size_t)b * TQ_ * HW_ * D_MODEL;
    float s = 0.f;
    for (int h = ch * 128; h < ch * 128 + 128; h++)
        s += y[base + (size_t)h * D_MODEL + d];
    part[(b * 8 + ch) * D_MODEL + d] = s;
}
__global__ void cls_p2_kernel(const float* __restrict__ part, float* __restrict__ y)
{
    int i = blockIdx.x * 256 + threadIdx.x;     // B*HW*D = 1048576
    int d = i & 255;
    int hw = (i >> 8) & (HW_ - 1);
    int b = i >> 18;
    float s = 0.f;
#pragma unroll
    for (int c = 0; c < 8; c++) s += part[(b * 8 + c) * D_MODEL + d];
    y[(size_t)b * TQ_ * HW_ * D_MODEL + (size_t)hw * D_MODEL + d] = s * (1.f / HW_);
}

// ---------------------------------------------------------------------------

template <typename OutT, bool GELU, bool RES>
static inline void run_gemm(const __nv_bfloat16* A, const __nv_bfloat16* W,
                            const float* bias, const float* res, OutT* C,
                            int M, int N, int K)
{
    cudaFuncSetAttribute(gemm_bf16_kernel<OutT, GELU, RES>,
                         cudaFuncAttributeMaxDynamicSharedMemorySize, SMEM_GEMM);
    gemm_bf16_kernel<OutT, GELU, RES><<<dim3(N / BN, M / BM), 256, SMEM_GEMM>>>(
        A, W, bias, res, C, M, N, K);
}

extern "C" void kernel_launch(void* const* d_in, const int* in_sizes, int n_in,
                              void* d_out, int out_size)
{
    const float* query = (const float*)d_in[0];
    const unsigned char* tmask = (const unsigned char*)d_in[2];
    const float* sln_g = (const float*)d_in[3];
    const float* sln_b = (const float*)d_in[4];
    const float* s_wq = (const float*)d_in[5];
    const float* s_bq = (const float*)d_in[6];
    const float* s_wk = (const float*)d_in[7];
    const float* s_bk = (const float*)d_in[8];
    const float* s_wv = (const float*)d_in[9];
    const float* s_bv = (const float*)d_in[10];
    const float* s_wo = (const float*)d_in[11];
    const float* s_bo = (const float*)d_in[12];
    const float* tln_g = (const float*)d_in[13];
    const float* tln_b = (const float*)d_in[14];
    const float* t_wq = (const float*)d_in[15];
    const float* t_bq = (const float*)d_in[16];
    const float* t_wk = (const float*)d_in[17];
    const float* t_bk = (const float*)d_in[18];
    const float* t_wv = (const float*)d_in[19];
    const float* t_bv = (const float*)d_in[20];
    const float* t_wo = (const float*)d_in[21];
    const float* t_bo = (const float*)d_in[22];
    const float* mln_g = (const float*)d_in[23];
    const float* mln_b = (const float*)d_in[24];
    const float* w1 = (const float*)d_in[25];
    const float* b1 = (const float*)d_in[26];
    const float* w2 = (const float*)d_in[27];
    const float* b2 = (const float*)d_in[28];
    float* out = (float*)d_out;

    __nv_bfloat16 *lnb, *qkvb, *aob, *hidb, *wsp, *wtp, *wso, *wto, *wb1, *wb2;
    float *x, *y, *tmp, *bsp, *btp, *clsp;
    cudaGetSymbolAddress((void**)&lnb,  g_lnb);
    cudaGetSymbolAddress((void**)&qkvb, g_qkvb);
    cudaGetSymbolAddress((void**)&aob,  g_aob);
    cudaGetSymbolAddress((void**)&x,    g_x);
    cudaGetSymbolAddress((void**)&y,    g_y);
    cudaGetSymbolAddress((void**)&tmp,  g_tmp);
    cudaGetSymbolAddress((void**)&hidb, g_hidb);
    cudaGetSymbolAddress((void**)&wsp,  g_wsp);
    cudaGetSymbolAddress((void**)&wtp,  g_wtp);
    cudaGetSymbolAddress((void**)&wso,  g_wso);
    cudaGetSymbolAddress((void**)&wto,  g_wto);
    cudaGetSymbolAddress((void**)&wb1,  g_w1);
    cudaGetSymbolAddress((void**)&wb2,  g_w2);
    cudaGetSymbolAddress((void**)&bsp,  g_bsp);
    cudaGetSymbolAddress((void**)&btp,  g_btp);
    cudaGetSymbolAddress((void**)&clsp, g_clsp);

    // ---- Prologue: one fused convert pack ----
    pack_all_kernel<<<1025, 256>>>(s_wq, s_wk, s_wv, t_wq, t_wk, t_wv, s_wo, t_wo, w1, w2,
                                   s_bq, s_bk, s_bv, t_bq, t_bk, t_bv,
                                   wsp, wtp, wso, wto, wb1, wb2, bsp, btp);

    // ---- Stage A: spatial windowed attention (frames 0..7) ----
    ln_kernel<<<MS / 8, 256>>>(query, lnb, sln_g, sln_b, MS, TQ_ * HW_, TS_ * HW_);
    run_gemm<__nv_bfloat16, false, false>(lnb, wsp, bsp, nullptr, qkvb, MS, 768, D_MODEL);
    spatial_attn_kernel<<<MS, 256>>>(qkvb, aob);
    run_gemm<float, false, false>(aob, wso, s_bo, nullptr, tmp, MS, D_MODEL, D_MODEL);
    assemble_x_kernel<<<MT * D_MODEL / 256, 256>>>(query, tmp, x);

    // ---- Stage B: temporal RoPE attention ----
    ln_kernel<<<MT / 8, 256>>>(x, lnb, tln_g, tln_b, MT, TQ_ * HW_, TQ_ * HW_);
    run_gemm<__nv_bfloat16, false, false>(lnb, wtp, btp, nullptr, qkvb, MT, 768, D_MODEL);
    temporal_attn_kernel<<<B_ * HW_, 256>>>(qkvb, tmask, aob);
    run_gemm<float, false, true>(aob, wto, t_bo, x, y, MT, D_MODEL, D_MODEL);

    // CLS frame averaging (two-phase, in place on y)
    cls_p1_kernel<<<B_ * 8, 256>>>(y, clsp);
    cls_p2_kernel<<<B_ * HW_ * D_MODEL / 256, 256>>>(clsp, y);

    // ---- Stage C: MLP ----
    ln_kernel<<<MT / 8, 256>>>(y, lnb, mln_g, mln_b, MT, TQ_ * HW_, TQ_ * HW_);
    run_gemm<__nv_bfloat16, true, false>(lnb, wb1, b1, nullptr, hidb, MT, MLP_, D_MODEL);
    run_gemm<float, false, true>(hidb, wb2, b2, y, out, MT, D_MODEL, MLP_);
}

// round 10
// speedup vs baseline: 1.2125x; 1.2125x over previous
#include <cuda_runtime.h>
#include <cuda_bf16.h>
#include <math.h>
#include <stdint.h>

// Problem constants
#define D_MODEL 256
#define B_      4
#define TQ_     9
#define TS_     8
#define HW_     1024
#define NH_     8
#define DH_     32
#define MLP_    1024

constexpr int MS = B_ * TS_ * HW_;   // 32768 spatial tokens
constexpr int MT = B_ * TQ_ * HW_;   // 36864 full tokens

// Scratch (device globals — no allocations allowed)
__device__ __align__(128) __nv_bfloat16 g_lnb [MT * D_MODEL];
__device__ __align__(128) __nv_bfloat16 g_qkvb[MT * 768];
__device__ __align__(128) __nv_bfloat16 g_aob [MT * D_MODEL];
__device__ __align__(128) float         g_x   [MT * D_MODEL];
__device__ __align__(128) float         g_y   [MT * D_MODEL];
__device__ __align__(128) float         g_tmp [MT * D_MODEL];
__device__ __align__(128) __nv_bfloat16 g_hidb[MT * MLP_];
// packed bf16 weights
__device__ __align__(128) __nv_bfloat16 g_wsp[D_MODEL * 768];
__device__ __align__(128) __nv_bfloat16 g_wtp[D_MODEL * 768];
__device__ __align__(128) __nv_bfloat16 g_wso[D_MODEL * D_MODEL];
__device__ __align__(128) __nv_bfloat16 g_wto[D_MODEL * D_MODEL];
__device__ __align__(128) __nv_bfloat16 g_w1 [D_MODEL * MLP_];
__device__ __align__(128) __nv_bfloat16 g_w2 [MLP_ * D_MODEL];
__device__ float g_bsp[768];
__device__ float g_btp[768];
__device__ float g_clsp[B_ * 8 * D_MODEL];

// ---------------------------------------------------------------------------
// Fused convert/pack: weights fp32 -> bf16 (keeping [K][N] layout), + biases
// ---------------------------------------------------------------------------
__global__ __launch_bounds__(256)
void pack_all_kernel(const float* __restrict__ s_wq, const float* __restrict__ s_wk,
                     const float* __restrict__ s_wv, const float* __restrict__ t_wq,
                     const float* __restrict__ t_wk, const float* __restrict__ t_wv,
                     const float* __restrict__ s_wo, const float* __restrict__ t_wo,
                     const float* __restrict__ w1,   const float* __restrict__ w2,
                     const float* __restrict__ s_bq, const float* __restrict__ s_bk,
                     const float* __restrict__ s_bv, const float* __restrict__ t_bq,
                     const float* __restrict__ t_bk, const float* __restrict__ t_bv,
                     __nv_bfloat16* __restrict__ wsp, __nv_bfloat16* __restrict__ wtp,
                     __nv_bfloat16* __restrict__ wso, __nv_bfloat16* __restrict__ wto,
                     __nv_bfloat16* __restrict__ wb1, __nv_bfloat16* __restrict__ wb2,
                     float* __restrict__ bsp, float* __restrict__ btp)
{
    int blk = blockIdx.x;
    int tid = threadIdx.x;
    if (blk >= 1024) {                      // bias pack block
        if (tid < 256) {
            bsp[tid] = s_bq[tid]; bsp[256 + tid] = s_bk[tid]; bsp[512 + tid] = s_bv[tid];
            btp[tid] = t_bq[tid]; btp[256 + tid] = t_bk[tid]; btp[512 + tid] = t_bv[tid];
        }
        return;
    }
    const float* src; __nv_bfloat16* dst;
    int t, Nsrc, Ndst, nOff;
    if (blk < 384) {                        // 6 x 64 blocks for qkv packs
        int m = blk / 64; t = blk % 64; Nsrc = 256; Ndst = 768;
        const float* s6[6] = {s_wq, s_wk, s_wv, t_wq, t_wk, t_wv};
        src = s6[m]; dst = (m < 3) ? wsp : wtp; nOff = (m % 3) * 256;
    } else if (blk < 448) { t = blk - 384; src = s_wo; dst = wso; Nsrc = 256;  Ndst = 256;  nOff = 0; }
    else   if (blk < 512) { t = blk - 448; src = t_wo; dst = wto; Nsrc = 256;  Ndst = 256;  nOff = 0; }
    else   if (blk < 768) { t = blk - 512; src = w1;   dst = wb1; Nsrc = 1024; Ndst = 1024; nOff = 0; }
    else                  { t = blk - 768; src = w2;   dst = wb2; Nsrc = 256;  Ndst = 256;  nOff = 0; }

    int i = t * 1024 + tid * 4;             // 1024 elems per block, 4 per thread
    const float4 v = *(const float4*)&src[i];
    int k = i / Nsrc, n = i - k * Nsrc;
    __nv_bfloat16* d = &dst[(size_t)k * Ndst + nOff + n];
    d[0] = __float2bfloat16(v.x); d[1] = __float2bfloat16(v.y);
    d[2] = __float2bfloat16(v.z); d[3] = __float2bfloat16(v.w);
}

// ---------------------------------------------------------------------------
// LayerNorm: one warp per token, bf16 output
// ---------------------------------------------------------------------------
__global__ void ln_kernel(const float* __restrict__ src, __nv_bfloat16* __restrict__ dst,
                          const float* __restrict__ gam, const float* __restrict__ bet,
                          int M, int src_tpb, int dst_tpb)
{
    int warp = (blockIdx.x * blockDim.x + threadIdx.x) >> 5;
    int lane = threadIdx.x & 31;
    if (warp >= M) return;
    int bb = warp / dst_tpb;
    int rem = warp % dst_tpb;
    const float* x = src + ((size_t)bb * src_tpb + rem) * D_MODEL;

    float vals[8];
    float s = 0.f, s2 = 0.f;
#pragma unroll
    for (int j = 0; j < 8; j++) {
        float v = x[lane + 32 * j];
        vals[j] = v; s += v; s2 += v * v;
    }
#pragma unroll
    for (int o = 16; o; o >>= 1) {
        s  += __shfl_xor_sync(0xffffffffu, s,  o);
        s2 += __shfl_xor_sync(0xffffffffu, s2, o);
    }
    float mean = s * (1.f / D_MODEL);
    float var  = s2 * (1.f / D_MODEL) - mean * mean;
    float rstd = rsqrtf(var + 1e-5f);

    __nv_bfloat16* y = dst + (size_t)warp * D_MODEL;
#pragma unroll
    for (int j = 0; j < 8; j++) {
        int d = lane + 32 * j;
        y[d] = __float2bfloat16((vals[j] - mean) * rstd * gam[d] + bet[d]);
    }
}

// ---------------------------------------------------------------------------
// bf16 mma.sync GEMM: C[M,N] = A[M,K] @ W[K,N] + bias (+ GELU / residual)
// Block 128x128, BK=64, 3-stage cp.async pipeline, one barrier per K-step.
// ---------------------------------------------------------------------------
#define BM 128
#define BN 128
#define BKB 64
#define A_PAD 72
#define B_PAD 136
#define A_STAGE_BYTES (BM * A_PAD * 2)
#define B_STAGE_BYTES (BKB * B_PAD * 2)
#define STAGE_BYTES   (A_STAGE_BYTES + B_STAGE_BYTES)
#define NSTAGE 3
#define SMEM_GEMM (STAGE_BYTES * NSTAGE)

#define CP_ASYNC16(dst_u32, src_ptr) \
    asm volatile("cp.async.cg.shared.global [%0], [%1], 16;\n" :: "r"(dst_u32), "l"(src_ptr))
#define CP_COMMIT() asm volatile("cp.async.commit_group;\n" ::: "memory")

__device__ __forceinline__ void ldmx4(uint32_t& r0, uint32_t& r1, uint32_t& r2, uint32_t& r3,
                                      const void* p)
{
    uint32_t a = (uint32_t)__cvta_generic_to_shared(p);
    asm volatile("ldmatrix.sync.aligned.m8n8.x4.shared.b16 {%0,%1,%2,%3}, [%4];"
                 : "=r"(r0), "=r"(r1), "=r"(r2), "=r"(r3) : "r"(a));
}
__device__ __forceinline__ void ldmx4t(uint32_t& r0, uint32_t& r1, uint32_t& r2, uint32_t& r3,
                                       const void* p)
{
    uint32_t a = (uint32_t)__cvta_generic_to_shared(p);
    asm volatile("ldmatrix.sync.aligned.m8n8.x4.trans.shared.b16 {%0,%1,%2,%3}, [%4];"
                 : "=r"(r0), "=r"(r1), "=r"(r2), "=r"(r3) : "r"(a));
}
__device__ __forceinline__ void mma_bf16(float* d, const uint32_t* a, const uint32_t* b)
{
    asm volatile(
        "mma.sync.aligned.m16n8k16.row.col.f32.bf16.bf16.f32 "
        "{%0,%1,%2,%3}, {%4,%5,%6,%7}, {%8,%9}, {%0,%1,%2,%3};"
        : "+f"(d[0]), "+f"(d[1]), "+f"(d[2]), "+f"(d[3])
        : "r"(a[0]), "r"(a[1]), "r"(a[2]), "r"(a[3]), "r"(b[0]), "r"(b[1]));
}

__device__ __forceinline__ void storeC(float* p, float v)          { *p = v; }
__device__ __forceinline__ void storeC(__nv_bfloat16* p, float v)  { *p = __float2bfloat16(v); }

template <typename OutT, bool GELU, bool RES>
__global__ __launch_bounds__(256)
void gemm_bf16_kernel(const __nv_bfloat16* __restrict__ A, const __nv_bfloat16* __restrict__ W,
                      const float* __restrict__ bias, const float* __restrict__ res,
                      OutT* __restrict__ C, int M, int N, int K)
{
    extern __shared__ char smem[];

    const int tid  = threadIdx.x;
    const int lane = tid & 31;
    const int warp = tid >> 5;
    const int wm   = warp & 1;
    const int wn   = warp >> 1;
    const int m0 = blockIdx.y * BM;
    const int n0 = blockIdx.x * BN;
    const int wmo = wm * 64;
    const int wno = wn * 32;

    const int aR = tid >> 1, aCb = (tid & 1) * 32;
    const int bR = tid >> 2, bCb = (tid & 3) * 8;

    float acc[4][4][4];
#pragma unroll
    for (int i = 0; i < 4; i++)
#pragma unroll
        for (int j = 0; j < 4; j++)
#pragma unroll
            for (int r = 0; r < 4; r++) acc[i][j][r] = 0.f;

    auto a_stage = [&](int s) -> __nv_bfloat16* {
        return (__nv_bfloat16*)(smem + (s % NSTAGE) * STAGE_BYTES);
    };
    auto b_stage = [&](int s) -> __nv_bfloat16* {
        return (__nv_bfloat16*)(smem + (s % NSTAGE) * STAGE_BYTES + A_STAGE_BYTES);
    };

    auto load_stage = [&](int s) {
        int k0 = s * BKB;
        __nv_bfloat16* As = a_stage(s);
        __nv_bfloat16* Bs = b_stage(s);
#pragma unroll
        for (int h = 0; h < 4; h++) {
            int c = aCb + h * 8;
            CP_ASYNC16((uint32_t)__cvta_generic_to_shared(&As[aR * A_PAD + c]),
                       A + (size_t)(m0 + aR) * K + k0 + c);
        }
#pragma unroll
        for (int h = 0; h < 4; h++) {
            int c = bCb + h * 32;
            CP_ASYNC16((uint32_t)__cvta_generic_to_shared(&Bs[bR * B_PAD + c]),
                       W + (size_t)(k0 + bR) * N + n0 + c);
        }
        CP_COMMIT();
    };

    auto compute_stage = [&](int s) {
        __nv_bfloat16* As = a_stage(s);
        __nv_bfloat16* Bs = b_stage(s);
#pragma unroll
        for (int ks = 0; ks < BKB; ks += 16) {
            uint32_t af[4][4];
            uint32_t bf[4][2];
#pragma unroll
            for (int mt = 0; mt < 4; mt++) {
                ldmx4(af[mt][0], af[mt][1], af[mt][2], af[mt][3],
                      &As[(wmo + mt * 16 + (lane & 15)) * A_PAD + ks + (lane >> 4) * 8]);
            }
#pragma unroll
            for (int ng = 0; ng < 2; ng++) {
                uint32_t t0, t1, t2, t3;
                ldmx4t(t0, t1, t2, t3,
                       &Bs[(ks + (lane & 15)) * B_PAD + wno + ng * 16 + (lane >> 4) * 8]);
                bf[ng * 2][0] = t0; bf[ng * 2][1] = t1;
                bf[ng * 2 + 1][0] = t2; bf[ng * 2 + 1][1] = t3;
            }
#pragma unroll
            for (int mt = 0; mt < 4; mt++)
#pragma unroll
                for (int nt = 0; nt < 4; nt++)
                    mma_bf16(acc[mt][nt], af[mt], bf[nt]);
        }
    };

    const int nst = K / BKB;
    load_stage(0);
    if (nst > 1) load_stage(1);

    for (int s = 0; s < nst; s++) {
        if (s + 1 < nst) asm volatile("cp.async.wait_group 1;" ::: "memory");
        else             asm volatile("cp.async.wait_group 0;" ::: "memory");
        __syncthreads();
        if (s + 2 < nst) load_stage(s + 2);
        compute_stage(s);
    }

#pragma unroll
    for (int mt = 0; mt < 4; mt++) {
#pragma unroll
        for (int nt = 0; nt < 4; nt++) {
            int row0 = m0 + wmo + mt * 16 + (lane >> 2);
            int col0 = n0 + wno + nt * 8 + 2 * (lane & 3);
#pragma unroll
            for (int r = 0; r < 4; r++) {
                int row = row0 + (r >> 1) * 8;
                int col = col0 + (r & 1);
                float v = acc[mt][nt][r] + bias[col];
                if (GELU) v = 0.5f * v * (1.f + erff(v * 0.70710678118654752f));
                if (RES)  v += res[(size_t)row * N + col];
                storeC(&C[(size_t)row * N + col], v);
            }
        }
    }
}

// ---------------------------------------------------------------------------
// bf16x4 helpers
// ---------------------------------------------------------------------------
__device__ __forceinline__ void bf4tof(uint2 raw, float* f)
{
    float2 lo = __bfloat1622float2(*(__nv_bfloat162*)&raw.x);
    float2 hi = __bfloat1622float2(*(__nv_bfloat162*)&raw.y);
    f[0] = lo.x; f[1] = lo.y; f[2] = hi.x; f[3] = hi.y;
}

// ---------------------------------------------------------------------------
// Spatial windowed attention: 4 tokens/block, warp = 4 heads x 8 lanes,
// lane holds 4 dims (bf16x4 loads). Score reduce = 3 shfls for 4 heads.
// ---------------------------------------------------------------------------
__global__ __launch_bounds__(256)
void spatial_attn_kernel(const __nv_bfloat16* __restrict__ QKV, __nv_bfloat16* __restrict__ O)
{
    const int w = threadIdx.x >> 5, lane = threadIdx.x & 31;
    const int hg = w * 4 + (lane >> 3);          // 0..31
    const int token = blockIdx.x * 4 + (hg >> 3);
    const int head = hg & 7;
    const int s4 = (lane & 7) * 4;               // dim offset within head
    const int hw = token & (HW_ - 1);
    const int r = hw >> 5, c = hw & 31;
    const float scale = 0.17677669529663687f;
    const __nv_bfloat16* qp = QKV + (size_t)token * 768 + head * DH_ + s4;

    float q[4];
    bf4tof(*(const uint2*)qp, q);

    float sc[9];
    float mx = -1e30f;
#pragma unroll
    for (int n = 0; n < 9; n++) {
        int dr = n / 3 - 1, dc = n % 3 - 1;
        int rr = r + dr, cc = c + dc;
        bool ok = (rr >= 0) & (rr < 32) & (cc >= 0) & (cc < 32);
        float p = 0.f;
        if (ok) {
            float k4[4];
            bf4tof(*(const uint2*)(qp + (long)(dr * 32 + dc) * 768 + 256), k4);
            p = q[0] * k4[0] + q[1] * k4[1] + q[2] * k4[2] + q[3] * k4[3];
        }
        p += __shfl_xor_sync(0xffffffffu, p, 1);
        p += __shfl_xor_sync(0xffffffffu, p, 2);
        p += __shfl_xor_sync(0xffffffffu, p, 4);
        sc[n] = ok ? p * scale : -1e9f;
        mx = fmaxf(mx, sc[n]);
    }
    float den = 0.f;
#pragma unroll
    for (int n = 0; n < 9; n++) { sc[n] = expf(sc[n] - mx); den += sc[n]; }
    float inv = 1.f / den;

    float o[4] = {0.f, 0.f, 0.f, 0.f};
#pragma unroll
    for (int n = 0; n < 9; n++) {
        int dr = n / 3 - 1, dc = n % 3 - 1;
        int rr = r + dr, cc = c + dc;
        bool ok = (rr >= 0) & (rr < 32) & (cc >= 0) & (cc < 32);
        if (ok) {
            float v4[4];
            bf4tof(*(const uint2*)(qp + (long)(dr * 32 + dc) * 768 + 512), v4);
            float wgt = sc[n] * inv;
            o[0] = fmaf(wgt, v4[0], o[0]); o[1] = fmaf(wgt, v4[1], o[1]);
            o[2] = fmaf(wgt, v4[2], o[2]); o[3] = fmaf(wgt, v4[3], o[3]);
        }
    }
    uint2 raw;
    __nv_bfloat162 lo; lo.x = __float2bfloat16(o[0]); lo.y = __float2bfloat16(o[1]);
    __nv_bfloat162 hi; hi.x = __float2bfloat16(o[2]); hi.y = __float2bfloat16(o[3]);
    raw.x = *(uint32_t*)&lo; raw.y = *(uint32_t*)&hi;
    *(uint2*)&O[(size_t)token * D_MODEL + head * DH_ + s4] = raw;
}

// ---------------------------------------------------------------------------
// Assemble x = concat(spatial_out + residual, last frame)
// ---------------------------------------------------------------------------
__global__ void assemble_x_kernel(const float* __restrict__ query,
                                  const float* __restrict__ sp,
                                  float* __restrict__ x)
{
    size_t i = (size_t)blockIdx.x * blockDim.x + threadIdx.x;
    const int per_bt = HW_ * D_MODEL;
    int bt = (int)(i / per_bt);
    int rem = (int)(i % per_bt);
    int b = bt / TQ_, t = bt % TQ_;
    float v = query[i];
    if (t < TS_) v += sp[(size_t)(b * TS_ + t) * per_bt + rem];
    x[i] = v;
}

// ---------------------------------------------------------------------------
// Temporal RoPE attention: 2 seqs/block, warp = 2 heads x 16 lanes,
// lane holds 2 dims (bf16x2). RoPE partner via shfl_xor(raw, 8).
// ---------------------------------------------------------------------------
__global__ __launch_bounds__(256)
void temporal_attn_kernel(const __nv_bfloat16* __restrict__ QKV,
                          const unsigned char* __restrict__ mask,
                          __nv_bfloat16* __restrict__ O)
{
    const int w = threadIdx.x >> 5, lane = threadIdx.x & 31;
    const int hg = w * 2 + (lane >> 4);          // 0..15
    const int seq = blockIdx.x * 2 + (hg >> 3);  // b*1024 + hw
    const int head = hg & 7;
    const int s = lane & 15;                     // dim pair index
    const int b = seq >> 10;
    const int hw = seq & (HW_ - 1);
    const size_t tstride = (size_t)HW_ * 768;
    const size_t base = ((size_t)(b * TQ_) * HW_ + hw) * 768 + head * DH_ + s * 2;
    const size_t ostride = (size_t)HW_ * D_MODEL;
    const size_t obase = ((size_t)(b * TQ_) * HW_ + hw) * D_MODEL + head * DH_ + s * 2;
    const float scale = 0.17677669529663687f;

    const float j0 = (float)((lane & 7) * 2);
    const float inv0 = powf(10000.f, -j0 / 16.f);
    const float inv1 = powf(10000.f, -(j0 + 1.f) / 16.f);
    const bool hi = (lane & 8) != 0;

    float qv[9][2], kv[9][2], vv[9][2];
#pragma unroll
    for (int t = 0; t < TQ_; t++) {
        uint32_t qr = *(const uint32_t*)&QKV[base + t * tstride];
        uint32_t kr = *(const uint32_t*)&QKV[base + 256 + t * tstride];
        uint32_t vr = *(const uint32_t*)&QKV[base + 512 + t * tstride];
        uint32_t qpr = __shfl_xor_sync(0xffffffffu, qr, 8);
        uint32_t kpr = __shfl_xor_sync(0xffffffffu, kr, 8);
        float2 qo = __bfloat1622float2(*(__nv_bfloat162*)&qr);
        float2 ko = __bfloat1622float2(*(__nv_bfloat162*)&kr);
        float2 vo = __bfloat1622float2(*(__nv_bfloat162*)&vr);
        float2 qq = __bfloat1622float2(*(__nv_bfloat162*)&qpr);
        float2 kk = __bfloat1622float2(*(__nv_bfloat162*)&kpr);
        float cs0, sn0, cs1, sn1;
        __sincosf((float)t * inv0, &sn0, &cs0);
        __sincosf((float)t * inv1, &sn1, &cs1);
        if (!hi) {      // own = x1, partner = x2:  x1*c - x2*s
            qv[t][0] = qo.x * cs0 - qq.x * sn0; qv[t][1] = qo.y * cs1 - qq.y * sn1;
            kv[t][0] = ko.x * cs0 - kk.x * sn0; kv[t][1] = ko.y * cs1 - kk.y * sn1;
        } else {        // own = x2, partner = x1:  x1*s + x2*c
            qv[t][0] = qq.x * sn0 + qo.x * cs0; qv[t][1] = qq.y * sn1 + qo.y * cs1;
            kv[t][0] = kk.x * sn0 + ko.x * cs0; kv[t][1] = kk.y * sn1 + ko.y * cs1;
        }
        vv[t][0] = vo.x; vv[t][1] = vo.y;
    }

#pragma unroll
    for (int tq = 0; tq < TQ_; tq++) {
        float sc[9];
        float mx = -1e30f;
#pragma unroll
        for (int tk = 0; tk < TQ_; tk++) {
            float p = qv[tq][0] * kv[tk][0] + qv[tq][1] * kv[tk][1];
            p += __shfl_xor_sync(0xffffffffu, p, 1);
            p += __shfl_xor_sync(0xffffffffu, p, 2);
            p += __shfl_xor_sync(0xffffffffu, p, 4);
            p += __shfl_xor_sync(0xffffffffu, p, 8);
            float sv = p * scale;
            if (mask[tq * TQ_ + tk]) sv = -1e9f;
            sc[tk] = sv;
            mx = fmaxf(mx, sv);
        }
        float den = 0.f;
#pragma unroll
        for (int tk = 0; tk < TQ_; tk++) { sc[tk] = expf(sc[tk] - mx); den += sc[tk]; }
        float invd = 1.f / den;
        float o0 = 0.f, o1 = 0.f;
#pragma unroll
        for (int tk = 0; tk < TQ_; tk++) {
            float wgt = sc[tk] * invd;
            o0 = fmaf(wgt, vv[tk][0], o0);
            o1 = fmaf(wgt, vv[tk][1], o1);
        }
        __nv_bfloat162 ob; ob.x = __float2bfloat16(o0); ob.y = __float2bfloat16(o1);
        *(uint32_t*)&O[obase + tq * ostride] = *(uint32_t*)&ob;
    }
}

// ---------------------------------------------------------------------------
// CLS frame averaging, two-phase deterministic
// ---------------------------------------------------------------------------
__global__ void cls_p1_kernel(const float* __restrict__ y, float* __restrict__ part)
{
    int blk = blockIdx.x;           // 32 blocks = (b, chunk)
    int b = blk >> 3, ch = blk & 7;
    int d = threadIdx.x;            // 256
    size_t base = (size_t)b * TQ_ * HW_ * D_MODEL;
    float s = 0.f;
    for (int h = ch * 128; h < ch * 128 + 128; h++)
        s += y[base + (size_t)h * D_MODEL + d];
    part[(b * 8 + ch) * D_MODEL + d] = s;
}
__global__ void cls_p2_kernel(const float* __restrict__ part, float* __restrict__ y)
{
    int i = blockIdx.x * 256 + threadIdx.x;     // B*HW*D = 1048576
    int d = i & 255;
    int hw = (i >> 8) & (HW_ - 1);
    int b = i >> 18;
    float s = 0.f;
#pragma unroll
    for (int c = 0; c < 8; c++) s += part[(b * 8 + c) * D_MODEL + d];
    y[(size_t)b * TQ_ * HW_ * D_MODEL + (size_t)hw * D_MODEL + d] = s * (1.f / HW_);
}

// ---------------------------------------------------------------------------

template <typename OutT, bool GELU, bool RES>
static inline void run_gemm(const __nv_bfloat16* A, const __nv_bfloat16* W,
                            const float* bias, const float* res, OutT* C,
                            int M, int N, int K)
{
    cudaFuncSetAttribute(gemm_bf16_kernel<OutT, GELU, RES>,
                         cudaFuncAttributeMaxDynamicSharedMemorySize, SMEM_GEMM);
    gemm_bf16_kernel<OutT, GELU, RES><<<dim3(N / BN, M / BM), 256, SMEM_GEMM>>>(
        A, W, bias, res, C, M, N, K);
}

extern "C" void kernel_launch(void* const* d_in, const int* in_sizes, int n_in,
                              void* d_out, int out_size)
{
    const float* query = (const float*)d_in[0];
    const unsigned char* tmask = (const unsigned char*)d_in[2];
    const float* sln_g = (const float*)d_in[3];
    const float* sln_b = (const float*)d_in[4];
    const float* s_wq = (const float*)d_in[5];
    const float* s_bq = (const float*)d_in[6];
    const float* s_wk = (const float*)d_in[7];
    const float* s_bk = (const float*)d_in[8];
    const float* s_wv = (const float*)d_in[9];
    const float* s_bv = (const float*)d_in[10];
    const float* s_wo = (const float*)d_in[11];
    const float* s_bo = (const float*)d_in[12];
    const float* tln_g = (const float*)d_in[13];
    const float* tln_b = (const float*)d_in[14];
    const float* t_wq = (const float*)d_in[15];
    const float* t_bq = (const float*)d_in[16];
    const float* t_wk = (const float*)d_in[17];
    const float* t_bk = (const float*)d_in[18];
    const float* t_wv = (const float*)d_in[19];
    const float* t_bv = (const float*)d_in[20];
    const float* t_wo = (const float*)d_in[21];
    const float* t_bo = (const float*)d_in[22];
    const float* mln_g = (const float*)d_in[23];
    const float* mln_b = (const float*)d_in[24];
    const float* w1 = (const float*)d_in[25];
    const float* b1 = (const float*)d_in[26];
    const float* w2 = (const float*)d_in[27];
    const float* b2 = (const float*)d_in[28];
    float* out = (float*)d_out;

    __nv_bfloat16 *lnb, *qkvb, *aob, *hidb, *wsp, *wtp, *wso, *wto, *wb1, *wb2;
    float *x, *y, *tmp, *bsp, *btp, *clsp;
    cudaGetSymbolAddress((void**)&lnb,  g_lnb);
    cudaGetSymbolAddress((void**)&qkvb, g_qkvb);
    cudaGetSymbolAddress((void**)&aob,  g_aob);
    cudaGetSymbolAddress((void**)&x,    g_x);
    cudaGetSymbolAddress((void**)&y,    g_y);
    cudaGetSymbolAddress((void**)&tmp,  g_tmp);
    cudaGetSymbolAddress((void**)&hidb, g_hidb);
    cudaGetSymbolAddress((void**)&wsp,  g_wsp);
    cudaGetSymbolAddress((void**)&wtp,  g_wtp);
    cudaGetSymbolAddress((void**)&wso,  g_wso);
    cudaGetSymbolAddress((void**)&wto,  g_wto);
    cudaGetSymbolAddress((void**)&wb1,  g_w1);
    cudaGetSymbolAddress((void**)&wb2,  g_w2);
    cudaGetSymbolAddress((void**)&bsp,  g_bsp);
    cudaGetSymbolAddress((void**)&btp,  g_btp);
    cudaGetSymbolAddress((void**)&clsp, g_clsp);

    // ---- Prologue: one fused convert pack ----
    pack_all_kernel<<<1025, 256>>>(s_wq, s_wk, s_wv, t_wq, t_wk, t_wv, s_wo, t_wo, w1, w2,
                                   s_bq, s_bk, s_bv, t_bq, t_bk, t_bv,
                                   wsp, wtp, wso, wto, wb1, wb2, bsp, btp);

    // ---- Stage A: spatial windowed attention (frames 0..7) ----
    ln_kernel<<<MS / 8, 256>>>(query, lnb, sln_g, sln_b, MS, TQ_ * HW_, TS_ * HW_);
    run_gemm<__nv_bfloat16, false, false>(lnb, wsp, bsp, nullptr, qkvb, MS, 768, D_MODEL);
    spatial_attn_kernel<<<MS / 4, 256>>>(qkvb, aob);
    run_gemm<float, false, false>(aob, wso, s_bo, nullptr, tmp, MS, D_MODEL, D_MODEL);
    assemble_x_kernel<<<MT * D_MODEL / 256, 256>>>(query, tmp, x);

    // ---- Stage B: temporal RoPE attention ----
    ln_kernel<<<MT / 8, 256>>>(x, lnb, tln_g, tln_b, MT, TQ_ * HW_, TQ_ * HW_);
    run_gemm<__nv_bfloat16, false, false>(lnb, wtp, btp, nullptr, qkvb, MT, 768, D_MODEL);
    temporal_attn_kernel<<<B_ * HW_ / 2, 256>>>(qkvb, tmask, aob);
    run_gemm<float, false, true>(aob, wto, t_bo, x, y, MT, D_MODEL, D_MODEL);

    // CLS frame averaging (two-phase, in place on y)
    cls_p1_kernel<<<B_ * 8, 256>>>(y, clsp);
    cls_p2_kernel<<<B_ * HW_ * D_MODEL / 256, 256>>>(clsp, y);

    // ---- Stage C: MLP ----
    ln_kernel<<<MT / 8, 256>>>(y, lnb, mln_g, mln_b, MT, TQ_ * HW_, TQ_ * HW_);
    run_gemm<__nv_bfloat16, true, false>(lnb, wb1, b1, nullptr, hidb, MT, MLP_, D_MODEL);
    run_gemm<float, false, true>(hidb, wb2, b2, y, out, MT, D_MODEL, MLP_);
}

// round 13
// speedup vs baseline: 1.2901x; 1.0640x over previous
#include <cuda_runtime.h>
#include <cuda_bf16.h>
#include <math.h>
#include <stdint.h>

// Problem constants
#define D_MODEL 256
#define B_      4
#define TQ_     9
#define TS_     8
#define HW_     1024
#define NH_     8
#define DH_     32
#define MLP_    1024

constexpr int MS = B_ * TS_ * HW_;   // 32768 spatial tokens
constexpr int MT = B_ * TQ_ * HW_;   // 36864 full tokens

// Scratch (device globals — no allocations allowed)
__device__ __align__(128) __nv_bfloat16 g_lnb [MT * D_MODEL];
__device__ __align__(128) __nv_bfloat16 g_qkvb[MT * 768];
__device__ __align__(128) __nv_bfloat16 g_aob [MT * D_MODEL];
__device__ __align__(128) float         g_x   [MT * D_MODEL];
__device__ __align__(128) float         g_y   [MT * D_MODEL];
__device__ __align__(128) __nv_bfloat16 g_hidb[MT * MLP_];
// packed bf16 weights
__device__ __align__(128) __nv_bfloat16 g_wsp[D_MODEL * 768];
__device__ __align__(128) __nv_bfloat16 g_wtp[D_MODEL * 768];
__device__ __align__(128) __nv_bfloat16 g_wso[D_MODEL * D_MODEL];
__device__ __align__(128) __nv_bfloat16 g_wto[D_MODEL * D_MODEL];
__device__ __align__(128) __nv_bfloat16 g_w1 [D_MODEL * MLP_];
__device__ __align__(128) __nv_bfloat16 g_w2 [MLP_ * D_MODEL];
__device__ float g_bsp[768];
__device__ float g_btp[768];
__device__ float g_clsp[B_ * 8 * D_MODEL];

// ---------------------------------------------------------------------------
// Fused convert/pack: weights fp32 -> bf16 (keeping [K][N] layout), + biases
// ---------------------------------------------------------------------------
__global__ __launch_bounds__(256)
void pack_all_kernel(const float* __restrict__ s_wq, const float* __restrict__ s_wk,
                     const float* __restrict__ s_wv, const float* __restrict__ t_wq,
                     const float* __restrict__ t_wk, const float* __restrict__ t_wv,
                     const float* __restrict__ s_wo, const float* __restrict__ t_wo,
                     const float* __restrict__ w1,   const float* __restrict__ w2,
                     const float* __restrict__ s_bq, const float* __restrict__ s_bk,
                     const float* __restrict__ s_bv, const float* __restrict__ t_bq,
                     const float* __restrict__ t_bk, const float* __restrict__ t_bv,
                     __nv_bfloat16* __restrict__ wsp, __nv_bfloat16* __restrict__ wtp,
                     __nv_bfloat16* __restrict__ wso, __nv_bfloat16* __restrict__ wto,
                     __nv_bfloat16* __restrict__ wb1, __nv_bfloat16* __restrict__ wb2,
                     float* __restrict__ bsp, float* __restrict__ btp)
{
    int blk = blockIdx.x;
    int tid = threadIdx.x;
    if (blk >= 1024) {                      // bias pack block
        if (tid < 256) {
            bsp[tid] = s_bq[tid]; bsp[256 + tid] = s_bk[tid]; bsp[512 + tid] = s_bv[tid];
            btp[tid] = t_bq[tid]; btp[256 + tid] = t_bk[tid]; btp[512 + tid] = t_bv[tid];
        }
        return;
    }
    const float* src; __nv_bfloat16* dst;
    int t, Nsrc, Ndst, nOff;
    if (blk < 384) {                        // 6 x 64 blocks for qkv packs
        int m = blk / 64; t = blk % 64; Nsrc = 256; Ndst = 768;
        const float* s6[6] = {s_wq, s_wk, s_wv, t_wq, t_wk, t_wv};
        src = s6[m]; dst = (m < 3) ? wsp : wtp; nOff = (m % 3) * 256;
    } else if (blk < 448) { t = blk - 384; src = s_wo; dst = wso; Nsrc = 256;  Ndst = 256;  nOff = 0; }
    else   if (blk < 512) { t = blk - 448; src = t_wo; dst = wto; Nsrc = 256;  Ndst = 256;  nOff = 0; }
    else   if (blk < 768) { t = blk - 512; src = w1;   dst = wb1; Nsrc = 1024; Ndst = 1024; nOff = 0; }
    else                  { t = blk - 768; src = w2;   dst = wb2; Nsrc = 256;  Ndst = 256;  nOff = 0; }

    int i = t * 1024 + tid * 4;
    const float4 v = *(const float4*)&src[i];
    int k = i / Nsrc, n = i - k * Nsrc;
    __nv_bfloat16* d = &dst[(size_t)k * Ndst + nOff + n];
    d[0] = __float2bfloat16(v.x); d[1] = __float2bfloat16(v.y);
    d[2] = __float2bfloat16(v.z); d[3] = __float2bfloat16(v.w);
}

// ---------------------------------------------------------------------------
// LayerNorm: one warp per token, bf16 output
// ---------------------------------------------------------------------------
__global__ void ln_kernel(const float* __restrict__ src, __nv_bfloat16* __restrict__ dst,
                          const float* __restrict__ gam, const float* __restrict__ bet,
                          int M, int src_tpb, int dst_tpb)
{
    int warp = (blockIdx.x * blockDim.x + threadIdx.x) >> 5;
    int lane = threadIdx.x & 31;
    if (warp >= M) return;
    int bb = warp / dst_tpb;
    int rem = warp % dst_tpb;
    const float* x = src + ((size_t)bb * src_tpb + rem) * D_MODEL;

    float vals[8];
    float s = 0.f, s2 = 0.f;
#pragma unroll
    for (int j = 0; j < 8; j++) {
        float v = x[lane + 32 * j];
        vals[j] = v; s += v; s2 += v * v;
    }
#pragma unroll
    for (int o = 16; o; o >>= 1) {
        s  += __shfl_xor_sync(0xffffffffu, s,  o);
        s2 += __shfl_xor_sync(0xffffffffu, s2, o);
    }
    float mean = s * (1.f / D_MODEL);
    float var  = s2 * (1.f / D_MODEL) - mean * mean;
    float rstd = rsqrtf(var + 1e-5f);

    __nv_bfloat16* y = dst + (size_t)warp * D_MODEL;
#pragma unroll
    for (int j = 0; j < 8; j++) {
        int d = lane + 32 * j;
        y[d] = __float2bfloat16((vals[j] - mean) * rstd * gam[d] + bet[d]);
    }
}

// ---------------------------------------------------------------------------
// bf16 mma.sync GEMM: C[M,N] = A[M,K] @ W[K,N] + bias (+ GELU / residual)
// Block 128x128, BK=64, 3-stage cp.async pipeline, one barrier per K-step.
// RESMODE: 0 = none, 1 = plain residual, 2 = spatial row-remap residual:
//   g = row + (row>>13)*1024; res read at res[g*N+col], C stored at C[g*N+col].
// NOTE: pads must be multiples of 8 bf16 (16B) for cp.async dst alignment.
// ---------------------------------------------------------------------------
#define BM 128
#define BN 128
#define BKB 64
#define A_PAD 72
#define B_PAD 136
#define A_STAGE_BYTES (BM * A_PAD * 2)          // 18432
#define B_STAGE_BYTES (BKB * B_PAD * 2)         // 17408
#define STAGE_BYTES   (A_STAGE_BYTES + B_STAGE_BYTES)
#define NSTAGE 3
#define SMEM_GEMM (STAGE_BYTES * NSTAGE)        // 107520 (x2 CTA = 215KB <= 228KB)

#define CP_ASYNC16(dst_u32, src_ptr) \
    asm volatile("cp.async.cg.shared.global [%0], [%1], 16;\n" :: "r"(dst_u32), "l"(src_ptr))
#define CP_COMMIT() asm volatile("cp.async.commit_group;\n" ::: "memory")

__device__ __forceinline__ void ldmx4(uint32_t& r0, uint32_t& r1, uint32_t& r2, uint32_t& r3,
                                      const void* p)
{
    uint32_t a = (uint32_t)__cvta_generic_to_shared(p);
    asm volatile("ldmatrix.sync.aligned.m8n8.x4.shared.b16 {%0,%1,%2,%3}, [%4];"
                 : "=r"(r0), "=r"(r1), "=r"(r2), "=r"(r3) : "r"(a));
}
__device__ __forceinline__ void ldmx4t(uint32_t& r0, uint32_t& r1, uint32_t& r2, uint32_t& r3,
                                       const void* p)
{
    uint32_t a = (uint32_t)__cvta_generic_to_shared(p);
    asm volatile("ldmatrix.sync.aligned.m8n8.x4.trans.shared.b16 {%0,%1,%2,%3}, [%4];"
                 : "=r"(r0), "=r"(r1), "=r"(r2), "=r"(r3) : "r"(a));
}
__device__ __forceinline__ void mma_bf16(float* d, const uint32_t* a, const uint32_t* b)
{
    asm volatile(
        "mma.sync.aligned.m16n8k16.row.col.f32.bf16.bf16.f32 "
        "{%0,%1,%2,%3}, {%4,%5,%6,%7}, {%8,%9}, {%0,%1,%2,%3};"
        : "+f"(d[0]), "+f"(d[1]), "+f"(d[2]), "+f"(d[3])
        : "r"(a[0]), "r"(a[1]), "r"(a[2]), "r"(a[3]), "r"(b[0]), "r"(b[1]));
}

__device__ __forceinline__ void storeC(float* p, float v)          { *p = v; }
__device__ __forceinline__ void storeC(__nv_bfloat16* p, float v)  { *p = __float2bfloat16(v); }

template <typename OutT, bool GELU, int RESMODE>
__global__ __launch_bounds__(256, 2)
void gemm_bf16_kernel(const __nv_bfloat16* __restrict__ A, const __nv_bfloat16* __restrict__ W,
                      const float* __restrict__ bias, const float* __restrict__ res,
                      OutT* __restrict__ C, int M, int N, int K)
{
    extern __shared__ char smem[];

    const int tid  = threadIdx.x;
    const int lane = tid & 31;
    const int warp = tid >> 5;
    const int wm   = warp & 1;
    const int wn   = warp >> 1;
    const int m0 = blockIdx.y * BM;
    const int n0 = blockIdx.x * BN;
    const int wmo = wm * 64;
    const int wno = wn * 32;

    const int aR = tid >> 1, aCb = (tid & 1) * 32;
    const int bR = tid >> 2, bCb = (tid & 3) * 8;

    float acc[4][4][4];
#pragma unroll
    for (int i = 0; i < 4; i++)
#pragma unroll
        for (int j = 0; j < 4; j++)
#pragma unroll
            for (int r = 0; r < 4; r++) acc[i][j][r] = 0.f;

    auto a_stage = [&](int s) -> __nv_bfloat16* {
        return (__nv_bfloat16*)(smem + (s % NSTAGE) * STAGE_BYTES);
    };
    auto b_stage = [&](int s) -> __nv_bfloat16* {
        return (__nv_bfloat16*)(smem + (s % NSTAGE) * STAGE_BYTES + A_STAGE_BYTES);
    };

    auto load_stage = [&](int s) {
        int k0 = s * BKB;
        __nv_bfloat16* As = a_stage(s);
        __nv_bfloat16* Bs = b_stage(s);
#pragma unroll
        for (int h = 0; h < 4; h++) {
            int c = aCb + h * 8;
            CP_ASYNC16((uint32_t)__cvta_generic_to_shared(&As[aR * A_PAD + c]),
                       A + (size_t)(m0 + aR) * K + k0 + c);
        }
#pragma unroll
        for (int h = 0; h < 4; h++) {
            int c = bCb + h * 32;
            CP_ASYNC16((uint32_t)__cvta_generic_to_shared(&Bs[bR * B_PAD + c]),
                       W + (size_t)(k0 + bR) * N + n0 + c);
        }
        CP_COMMIT();
    };

    auto compute_stage = [&](int s) {
        __nv_bfloat16* As = a_stage(s);
        __nv_bfloat16* Bs = b_stage(s);
#pragma unroll
        for (int ks = 0; ks < BKB; ks += 16) {
            uint32_t af[4][4];
            uint32_t bf[4][2];
#pragma unroll
            for (int mt = 0; mt < 4; mt++) {
                ldmx4(af[mt][0], af[mt][1], af[mt][2], af[mt][3],
                      &As[(wmo + mt * 16 + (lane & 15)) * A_PAD + ks + (lane >> 4) * 8]);
            }
#pragma unroll
            for (int ng = 0; ng < 2; ng++) {
                uint32_t t0, t1, t2, t3;
                ldmx4t(t0, t1, t2, t3,
                       &Bs[(ks + (lane & 15)) * B_PAD + wno + ng * 16 + (lane >> 4) * 8]);
                bf[ng * 2][0] = t0; bf[ng * 2][1] = t1;
                bf[ng * 2 + 1][0] = t2; bf[ng * 2 + 1][1] = t3;
            }
#pragma unroll
            for (int mt = 0; mt < 4; mt++)
#pragma unroll
                for (int nt = 0; nt < 4; nt++)
                    mma_bf16(acc[mt][nt], af[mt], bf[nt]);
        }
    };

    const int nst = K / BKB;
    load_stage(0);
    if (nst > 1) load_stage(1);

    for (int s = 0; s < nst; s++) {
        if (s + 1 < nst) asm volatile("cp.async.wait_group 1;" ::: "memory");
        else             asm volatile("cp.async.wait_group 0;" ::: "memory");
        __syncthreads();
        if (s + 2 < nst) load_stage(s + 2);
        compute_stage(s);
    }

#pragma unroll
    for (int mt = 0; mt < 4; mt++) {
#pragma unroll
        for (int nt = 0; nt < 4; nt++) {
            int row0 = m0 + wmo + mt * 16 + (lane >> 2);
            int col0 = n0 + wno + nt * 8 + 2 * (lane & 3);
#pragma unroll
            for (int r = 0; r < 4; r++) {
                int row = row0 + (r >> 1) * 8;
                int col = col0 + (r & 1);
                float v = acc[mt][nt][r] + bias[col];
                if (GELU) v = 0.5f * v * (1.f + erff(v * 0.70710678118654752f));
                int g = (RESMODE == 2) ? (row + (row >> 13) * 1024) : row;
                if (RESMODE != 0) v += res[(size_t)g * N + col];
                storeC(&C[(size_t)g * N + col], v);
            }
        }
    }
}

// ---------------------------------------------------------------------------
// Last-frame copy: x rows (b*9+8)*1024+hw <- query (fp32, 4MB)
// ---------------------------------------------------------------------------
__global__ void lastframe_kernel(const float* __restrict__ query, float* __restrict__ x)
{
    int e = blockIdx.x * 256 + threadIdx.x;         // float4 index
    int row = e >> 6;                               // 64 float4 per row, row 0..4095
    int b = row >> 10, hw = row & 1023;
    size_t grow = ((size_t)(b * TQ_ + TS_) * HW_ + hw) * D_MODEL + (e & 63) * 4;
    *(float4*)&x[grow] = *(const float4*)&query[grow];
}

// ---------------------------------------------------------------------------
// Spatial windowed attention v3: warp = 1 token (8 heads x 4 lanes),
// lane holds 8 dims (uint4 loads). Score reduce = 2 shfls.
// ---------------------------------------------------------------------------
__device__ __forceinline__ void bf8tof(uint4 raw, float* f)
{
    float2 a = __bfloat1622float2(*(__nv_bfloat162*)&raw.x);
    float2 b = __bfloat1622float2(*(__nv_bfloat162*)&raw.y);
    float2 c = __bfloat1622float2(*(__nv_bfloat162*)&raw.z);
    float2 d = __bfloat1622float2(*(__nv_bfloat162*)&raw.w);
    f[0] = a.x; f[1] = a.y; f[2] = b.x; f[3] = b.y;
    f[4] = c.x; f[5] = c.y; f[6] = d.x; f[7] = d.y;
}

__global__ __launch_bounds__(256)
void spatial_attn_kernel(const __nv_bfloat16* __restrict__ QKV, __nv_bfloat16* __restrict__ O)
{
    const int w = threadIdx.x >> 5, lane = threadIdx.x & 31;
    const int token = blockIdx.x * 8 + w;
    const int head = lane >> 2;
    const int s8 = (lane & 3) * 8;
    const int hw = token & (HW_ - 1);
    const int r = hw >> 5, c = hw & 31;
    const float scale = 0.17677669529663687f;
    const __nv_bfloat16* qp = QKV + (size_t)token * 768 + head * DH_ + s8;

    float q[8];
    bf8tof(*(const uint4*)qp, q);

    float sc[9];
    float mx = -1e30f;
#pragma unroll
    for (int n = 0; n < 9; n++) {
        int dr = n / 3 - 1, dc = n % 3 - 1;
        int rr = r + dr, cc = c + dc;
        bool ok = (rr >= 0) & (rr < 32) & (cc >= 0) & (cc < 32);
        float p = 0.f;
        if (ok) {
            float k8[8];
            bf8tof(*(const uint4*)(qp + (long)(dr * 32 + dc) * 768 + 256), k8);
#pragma unroll
            for (int d = 0; d < 8; d++) p = fmaf(q[d], k8[d], p);
        }
        p += __shfl_xor_sync(0xffffffffu, p, 1);
        p += __shfl_xor_sync(0xffffffffu, p, 2);
        sc[n] = ok ? p * scale : -1e9f;
        mx = fmaxf(mx, sc[n]);
    }
    float den = 0.f;
#pragma unroll
    for (int n = 0; n < 9; n++) { sc[n] = expf(sc[n] - mx); den += sc[n]; }
    float inv = 1.f / den;

    float o[8] = {};
#pragma unroll
    for (int n = 0; n < 9; n++) {
        int dr = n / 3 - 1, dc = n % 3 - 1;
        int rr = r + dr, cc = c + dc;
        bool ok = (rr >= 0) & (rr < 32) & (cc >= 0) & (cc < 32);
        if (ok) {
            float v8[8];
            bf8tof(*(const uint4*)(qp + (long)(dr * 32 + dc) * 768 + 512), v8);
            float wgt = sc[n] * inv;
#pragma unroll
            for (int d = 0; d < 8; d++) o[d] = fmaf(wgt, v8[d], o[d]);
        }
    }
    uint4 raw;
    __nv_bfloat162 p0; p0.x = __float2bfloat16(o[0]); p0.y = __float2bfloat16(o[1]);
    __nv_bfloat162 p1; p1.x = __float2bfloat16(o[2]); p1.y = __float2bfloat16(o[3]);
    __nv_bfloat162 p2; p2.x = __float2bfloat16(o[4]); p2.y = __float2bfloat16(o[5]);
    __nv_bfloat162 p3; p3.x = __float2bfloat16(o[6]); p3.y = __float2bfloat16(o[7]);
    raw.x = *(uint32_t*)&p0; raw.y = *(uint32_t*)&p1;
    raw.z = *(uint32_t*)&p2; raw.w = *(uint32_t*)&p3;
    *(uint4*)&O[(size_t)token * D_MODEL + head * DH_ + s8] = raw;
}

// ---------------------------------------------------------------------------
// Temporal RoPE attention: 2 seqs/block, warp = 2 heads x 16 lanes,
// lane holds 2 dims (bf16x2). RoPE partner via shfl_xor(raw, 8).
// ---------------------------------------------------------------------------
__global__ __launch_bounds__(256)
void temporal_attn_kernel(const __nv_bfloat16* __restrict__ QKV,
                          const unsigned char* __restrict__ mask,
                          __nv_bfloat16* __restrict__ O)
{
    const int w = threadIdx.x >> 5, lane = threadIdx.x & 31;
    const int hg = w * 2 + (lane >> 4);          // 0..15
    const int seq = blockIdx.x * 2 + (hg >> 3);  // b*1024 + hw
    const int head = hg & 7;
    const int s = lane & 15;                     // dim pair index
    const int b = seq >> 10;
    const int hw = seq & (HW_ - 1);
    const size_t tstride = (size_t)HW_ * 768;
    const size_t base = ((size_t)(b * TQ_) * HW_ + hw) * 768 + head * DH_ + s * 2;
    const size_t ostride = (size_t)HW_ * D_MODEL;
    const size_t obase = ((size_t)(b * TQ_) * HW_ + hw) * D_MODEL + head * DH_ + s * 2;
    const float scale = 0.17677669529663687f;

    const float j0 = (float)((lane & 7) * 2);
    const float inv0 = powf(10000.f, -j0 / 16.f);
    const float inv1 = powf(10000.f, -(j0 + 1.f) / 16.f);
    const bool hi = (lane & 8) != 0;

    float qv[9][2], kv[9][2], vv[9][2];
#pragma unroll
    for (int t = 0; t < TQ_; t++) {
        uint32_t qr = *(const uint32_t*)&QKV[base + t * tstride];
        uint32_t kr = *(const uint32_t*)&QKV[base + 256 + t * tstride];
        uint32_t vr = *(const uint32_t*)&QKV[base + 512 + t * tstride];
        uint32_t qpr = __shfl_xor_sync(0xffffffffu, qr, 8);
        uint32_t kpr = __shfl_xor_sync(0xffffffffu, kr, 8);
        float2 qo = __bfloat1622float2(*(__nv_bfloat162*)&qr);
        float2 ko = __bfloat1622float2(*(__nv_bfloat162*)&kr);
        float2 vo = __bfloat1622float2(*(__nv_bfloat162*)&vr);
        float2 qq = __bfloat1622float2(*(__nv_bfloat162*)&qpr);
        float2 kk = __bfloat1622float2(*(__nv_bfloat162*)&kpr);
        float cs0, sn0, cs1, sn1;
        __sincosf((float)t * inv0, &sn0, &cs0);
        __sincosf((float)t * inv1, &sn1, &cs1);
        if (!hi) {
            qv[t][0] = qo.x * cs0 - qq.x * sn0; qv[t][1] = qo.y * cs1 - qq.y * sn1;
            kv[t][0] = ko.x * cs0 - kk.x * sn0; kv[t][1] = ko.y * cs1 - kk.y * sn1;
        } else {
            qv[t][0] = qq.x * sn0 + qo.x * cs0; qv[t][1] = qq.y * sn1 + qo.y * cs1;
            kv[t][0] = kk.x * sn0 + ko.x * cs0; kv[t][1] = kk.y * sn1 + ko.y * cs1;
        }
        vv[t][0] = vo.x; vv[t][1] = vo.y;
    }

#pragma unroll
    for (int tq = 0; tq < TQ_; tq++) {
        float sc[9];
        float mx = -1e30f;
#pragma unroll
        for (int tk = 0; tk < TQ_; tk++) {
            float p = qv[tq][0] * kv[tk][0] + qv[tq][1] * kv[tk][1];
            p += __shfl_xor_sync(0xffffffffu, p, 1);
            p += __shfl_xor_sync(0xffffffffu, p, 2);
            p += __shfl_xor_sync(0xffffffffu, p, 4);
            p += __shfl_xor_sync(0xffffffffu, p, 8);
            float sv = p * scale;
            if (mask[tq * TQ_ + tk]) sv = -1e9f;
            sc[tk] = sv;
            mx = fmaxf(mx, sv);
        }
        float den = 0.f;
#pragma unroll
        for (int tk = 0; tk < TQ_; tk++) { sc[tk] = expf(sc[tk] - mx); den += sc[tk]; }
        float invd = 1.f / den;
        float o0 = 0.f, o1 = 0.f;
#pragma unroll
        for (int tk = 0; tk < TQ_; tk++) {
            float wgt = sc[tk] * invd;
            o0 = fmaf(wgt, vv[tk][0], o0);
            o1 = fmaf(wgt, vv[tk][1], o1);
        }
        __nv_bfloat162 ob; ob.x = __float2bfloat16(o0); ob.y = __float2bfloat16(o1);
        *(uint32_t*)&O[obase + tq * ostride] = *(uint32_t*)&ob;
    }
}

// ---------------------------------------------------------------------------
// CLS frame averaging, two-phase deterministic
// ---------------------------------------------------------------------------
__global__ void cls_p1_kernel(const float* __restrict__ y, float* __restrict__ part)
{
    int blk = blockIdx.x;
    int b = blk >> 3, ch = blk & 7;
    int d = threadIdx.x;
    size_t base = (size_t)b * TQ_ * HW_ * D_MODEL;
    float s = 0.f;
    for (int h = ch * 128; h < ch * 128 + 128; h++)
        s += y[base + (size_t)h * D_MODEL + d];
    part[(b * 8 + ch) * D_MODEL + d] = s;
}
__global__ void cls_p2_kernel(const float* __restrict__ part, float* __restrict__ y)
{
    int i = blockIdx.x * 256 + threadIdx.x;
    int d = i & 255;
    int hw = (i >> 8) & (HW_ - 1);
    int b = i >> 18;
    float s = 0.f;
#pragma unroll
    for (int c = 0; c < 8; c++) s += part[(b * 8 + c) * D_MODEL + d];
    y[(size_t)b * TQ_ * HW_ * D_MODEL + (size_t)hw * D_MODEL + d] = s * (1.f / HW_);
}

// ---------------------------------------------------------------------------

template <typename OutT, bool GELU, int RESMODE>
static inline void run_gemm(const __nv_bfloat16* A, const __nv_bfloat16* W,
                            const float* bias, const float* res, OutT* C,
                            int M, int N, int K)
{
    cudaFuncSetAttribute(gemm_bf16_kernel<OutT, GELU, RESMODE>,
                         cudaFuncAttributeMaxDynamicSharedMemorySize, SMEM_GEMM);
    gemm_bf16_kernel<OutT, GELU, RESMODE><<<dim3(N / BN, M / BM), 256, SMEM_GEMM>>>(
        A, W, bias, res, C, M, N, K);
}

extern "C" void kernel_launch(void* const* d_in, const int* in_sizes, int n_in,
                              void* d_out, int out_size)
{
    const float* query = (const float*)d_in[0];
    const unsigned char* tmask = (const unsigned char*)d_in[2];
    const float* sln_g = (const float*)d_in[3];
    const float* sln_b = (const float*)d_in[4];
    const float* s_wq = (const float*)d_in[5];
    const float* s_bq = (const float*)d_in[6];
    const float* s_wk = (const float*)d_in[7];
    const float* s_bk = (const float*)d_in[8];
    const float* s_wv = (const float*)d_in[9];
    const float* s_bv = (const float*)d_in[10];
    const float* s_wo = (const float*)d_in[11];
    const float* s_bo = (const float*)d_in[12];
    const float* tln_g = (const float*)d_in[13];
    const float* tln_b = (const float*)d_in[14];
    const float* t_wq = (const float*)d_in[15];
    const float* t_bq = (const float*)d_in[16];
    const float* t_wk = (const float*)d_in[17];
    const float* t_bk = (const float*)d_in[18];
    const float* t_wv = (const float*)d_in[19];
    const float* t_bv = (const float*)d_in[20];
    const float* t_wo = (const float*)d_in[21];
    const float* t_bo = (const float*)d_in[22];
    const float* mln_g = (const float*)d_in[23];
    const float* mln_b = (const float*)d_in[24];
    const float* w1 = (const float*)d_in[25];
    const float* b1 = (const float*)d_in[26];
    const float* w2 = (const float*)d_in[27];
    const float* b2 = (const float*)d_in[28];
    float* out = (float*)d_out;

    __nv_bfloat16 *lnb, *qkvb, *aob, *hidb, *wsp, *wtp, *wso, *wto, *wb1, *wb2;
    float *x, *y, *bsp, *btp, *clsp;
    cudaGetSymbolAddress((void**)&lnb,  g_lnb);
    cudaGetSymbolAddress((void**)&qkvb, g_qkvb);
    cudaGetSymbolAddress((void**)&aob,  g_aob);
    cudaGetSymbolAddress((void**)&x,    g_x);
    cudaGetSymbolAddress((void**)&y,    g_y);
    cudaGetSymbolAddress((void**)&hidb, g_hidb);
    cudaGetSymbolAddress((void**)&wsp,  g_wsp);
    cudaGetSymbolAddress((void**)&wtp,  g_wtp);
    cudaGetSymbolAddress((void**)&wso,  g_wso);
    cudaGetSymbolAddress((void**)&wto,  g_wto);
    cudaGetSymbolAddress((void**)&wb1,  g_w1);
    cudaGetSymbolAddress((void**)&wb2,  g_w2);
    cudaGetSymbolAddress((void**)&bsp,  g_bsp);
    cudaGetSymbolAddress((void**)&btp,  g_btp);
    cudaGetSymbolAddress((void**)&clsp, g_clsp);

    // ---- Prologue: one fused convert pack ----
    pack_all_kernel<<<1025, 256>>>(s_wq, s_wk, s_wv, t_wq, t_wk, t_wv, s_wo, t_wo, w1, w2,
                                   s_bq, s_bk, s_bv, t_bq, t_bk, t_bv,
                                   wsp, wtp, wso, wto, wb1, wb2, bsp, btp);

    // ---- Stage A: spatial windowed attention (frames 0..7) ----
    ln_kernel<<<MS / 8, 256>>>(query, lnb, sln_g, sln_b, MS, TQ_ * HW_, TS_ * HW_);
    run_gemm<__nv_bfloat16, false, 0>(lnb, wsp, bsp, nullptr, qkvb, MS, 768, D_MODEL);
    spatial_attn_kernel<<<MS / 8, 256>>>(qkvb, aob);
    // O-proj fused with residual-from-query and spatial->full row remap (writes x)
    run_gemm<float, false, 2>(aob, wso, s_bo, query, x, MS, D_MODEL, D_MODEL);
    lastframe_kernel<<<1024, 256>>>(query, x);

    // ---- Stage B: temporal RoPE attention ----
    ln_kernel<<<MT / 8, 256>>>(x, lnb, tln_g, tln_b, MT, TQ_ * HW_, TQ_ * HW_);
    run_gemm<__nv_bfloat16, false, 0>(lnb, wtp, btp, nullptr, qkvb, MT, 768, D_MODEL);
    temporal_attn_kernel<<<B_ * HW_ / 2, 256>>>(qkvb, tmask, aob);
    run_gemm<float, false, 1>(aob, wto, t_bo, x, y, MT, D_MODEL, D_MODEL);

    // CLS frame averaging (two-phase, in place on y)
    cls_p1_kernel<<<B_ * 8, 256>>>(y, clsp);
    cls_p2_kernel<<<B_ * HW_ * D_MODEL / 256, 256>>>(clsp, y);

    // ---- Stage C: MLP ----
    ln_kernel<<<MT / 8, 256>>>(y, lnb, mln_g, mln_b, MT, TQ_ * HW_, TQ_ * HW_);
    run_gemm<__nv_bfloat16, true, 0>(lnb, wb1, b1, nullptr, hidb, MT, MLP_, D_MODEL);
    run_gemm<float, false, 1>(hidb, wb2, b2, y, out, MT, D_MODEL, MLP_);
}